// round 1
// baseline (speedup 1.0000x reference)
#include <cuda_runtime.h>

#define FULL_MASK 0xffffffffu
#define NEG_K 20           // negatives per example (fixed by the problem)
#define SCORES 21          // 20 negatives + 1 positive

// Scratch accumulator (device global — no allocations allowed).
__device__ double g_accum;

__global__ void zero_kernel() { g_accum = 0.0; }

__global__ void finalize_kernel(float* __restrict__ out, int B) {
    // loss = -( sum of log-sigmoid terms ) / B
    out[0] = (float)(-g_accum / (double)B);
}

// One warp per example. E = 128 = 32 lanes x float4.
__global__ __launch_bounds__(256)
void skipgram_kernel(const int* __restrict__ in_b,
                     const int* __restrict__ out_b,
                     const int* __restrict__ neg,
                     const float* __restrict__ iemb,
                     const float* __restrict__ oemb,
                     int B)
{
    const int warp = (blockIdx.x * blockDim.x + threadIdx.x) >> 5;
    const int lane = threadIdx.x & 31;

    float warp_loss = 0.0f;

    if (warp < B) {
        const int b = warp;

        // Lane-distributed index fetch: lanes 0..19 hold negative indices,
        // lane 20 holds the positive (output_batch) index.
        int idx_all = 0;
        if (lane < NEG_K)       idx_all = neg[(size_t)b * NEG_K + lane];
        else if (lane == NEG_K) idx_all = out_b[b];

        const int ii = in_b[b];  // uniform across warp

        const float4* __restrict__ ibase = reinterpret_cast<const float4*>(iemb);
        const float4* __restrict__ obase = reinterpret_cast<const float4*>(oemb);

        // Input-embedding row chunk for this lane.
        const float4 iv = __ldg(ibase + (size_t)ii * 32 + lane);

        // Per-lane dot partials for all 21 scores (padded to 32 for the
        // halving-exchange reduction).
        float p[32];
        #pragma unroll
        for (int k = 0; k < SCORES; k++) {
            const int ridx = __shfl_sync(FULL_MASK, idx_all, k);
            const float4 rv = __ldg(obase + (size_t)ridx * 32 + lane);
            p[k] = rv.x * iv.x + rv.y * iv.y + rv.z * iv.z + rv.w * iv.w;
        }
        #pragma unroll
        for (int k = SCORES; k < 32; k++) p[k] = 0.0f;

        // Transpose-reduce: 5 halving-exchange rounds (31 SHFL total).
        // Invariant: after the round with width w, lane holds partial sums
        // (over 32/w lanes... inductively) for scores base..base+w-1 where
        // base accumulates the lane's high bits. Final: lane L holds the
        // fully reduced score L.
        #pragma unroll
        for (int w = 16; w >= 1; w >>= 1) {
            const bool hi = (lane & w) != 0;
            #pragma unroll
            for (int k = 0; k < w; k++) {
                const float send = hi ? p[k]     : p[k + w];
                const float keep = hi ? p[k + w] : p[k];
                const float t = __shfl_xor_sync(FULL_MASK, send, w);
                p[k] = keep + t;
            }
        }
        const float score = p[0];  // lane L holds score L

        // log_sigmoid, one warp-wide pass:
        //   lanes 0..19: log_sigmoid(-neg_score), lane 20: log_sigmoid(+pos_score)
        // stable form: logsig(x) = min(x,0) - log(1 + exp(-|x|))
        const float x  = (lane < NEG_K) ? -score : score;
        const float ax = fabsf(x);
        float ls = fminf(x, 0.0f) - __logf(1.0f + __expf(-ax));
        if (lane > NEG_K) ls = 0.0f;

        // Warp-sum of the 21 log-sigmoid terms.
        #pragma unroll
        for (int w = 16; w >= 1; w >>= 1)
            ls += __shfl_xor_sync(FULL_MASK, ls, w);

        warp_loss = ls;  // sum of logsig terms for this example (<= 0)
    }

    // Block reduction: 8 warps -> one double atomic per block.
    __shared__ float wl[8];
    const int wib = threadIdx.x >> 5;
    if (lane == 0) wl[wib] = warp_loss;
    __syncthreads();
    if (threadIdx.x == 0) {
        double s = 0.0;
        #pragma unroll
        for (int i = 0; i < 8; i++) s += (double)wl[i];
        atomicAdd(&g_accum, s);
    }
}

extern "C" void kernel_launch(void* const* d_in, const int* in_sizes, int n_in,
                              void* d_out, int out_size) {
    const int*   in_b  = (const int*)  d_in[0];
    const int*   out_b = (const int*)  d_in[1];
    const int*   neg   = (const int*)  d_in[2];
    const float* iemb  = (const float*)d_in[3];
    const float* oemb  = (const float*)d_in[4];

    const int B = in_sizes[0];  // 65536

    zero_kernel<<<1, 1>>>();

    const int threads = 256;
    const int warps_per_block = threads / 32;
    const int blocks = (B + warps_per_block - 1) / warps_per_block;
    skipgram_kernel<<<blocks, threads>>>(in_b, out_b, neg, iemb, oemb, B);

    finalize_kernel<<<1, 1>>>((float*)d_out, B);
}

// round 2
// speedup vs baseline: 1.1169x; 1.1169x over previous
#include <cuda_runtime.h>
#include <cuda_fp16.h>

#define FULL_MASK 0xffffffffu
#define NEG_K 20           // negatives per example (fixed by the problem)
#define SCORES 21          // 20 negatives + 1 positive
#define VOCAB 100000
#define EMBED 128

// Scratch (device globals — no allocations allowed).
__device__ __half       g_oemb_h[VOCAB * EMBED];   // fp16 copy of output_emb (25.6 MB)
__device__ double       g_accum  = 0.0;            // loss accumulator
__device__ unsigned int g_ticket = 0;              // last-block ticket

// ---------------------------------------------------------------------------
// Convert output_emb fp32 -> fp16 (runs every replay; pure function of input).
// Each thread handles 8 elements: 2x float4 in, 1x uint4 (8 halves) out.
// ---------------------------------------------------------------------------
__global__ __launch_bounds__(256)
void convert_kernel(const float* __restrict__ oemb) {
    const int n8 = (VOCAB * EMBED) / 8;
    int i = blockIdx.x * blockDim.x + threadIdx.x;
    if (i >= n8) return;

    const float4* __restrict__ src = reinterpret_cast<const float4*>(oemb);
    float4 a = __ldg(src + 2 * i);
    float4 b = __ldg(src + 2 * i + 1);

    __half2 h0 = __floats2half2_rn(a.x, a.y);
    __half2 h1 = __floats2half2_rn(a.z, a.w);
    __half2 h2 = __floats2half2_rn(b.x, b.y);
    __half2 h3 = __floats2half2_rn(b.z, b.w);

    uint4 v;
    v.x = *reinterpret_cast<unsigned int*>(&h0);
    v.y = *reinterpret_cast<unsigned int*>(&h1);
    v.z = *reinterpret_cast<unsigned int*>(&h2);
    v.w = *reinterpret_cast<unsigned int*>(&h3);
    reinterpret_cast<uint4*>(g_oemb_h)[i] = v;
}

// ---------------------------------------------------------------------------
// Main kernel: one warp per example.
//   input row:  fp32, 128 floats -> float4 per lane (dims [4l, 4l+4))
//   output rows: fp16, 128 halves -> uint2 (4 halves) per lane, same dims
// Last block finalizes: out[0] = -sum / B, then resets accumulator state.
// ---------------------------------------------------------------------------
__global__ __launch_bounds__(256)
void skipgram_kernel(const int* __restrict__ in_b,
                     const int* __restrict__ out_b,
                     const int* __restrict__ neg,
                     const float* __restrict__ iemb,
                     float* __restrict__ out,
                     int B)
{
    const int warp = (blockIdx.x * blockDim.x + threadIdx.x) >> 5;
    const int lane = threadIdx.x & 31;

    float warp_loss = 0.0f;

    if (warp < B) {
        const int b = warp;

        // Lane-distributed index fetch: lanes 0..19 = negatives, lane 20 = positive.
        int idx_all = 0;
        if (lane < NEG_K)       idx_all = neg[(size_t)b * NEG_K + lane];
        else if (lane == NEG_K) idx_all = out_b[b];

        const int ii = in_b[b];  // uniform across warp

        // Input-embedding chunk for this lane (fp32), converted to half2 pair
        // for HFMA2 dot-product math.
        const float4 iv = __ldg(reinterpret_cast<const float4*>(iemb) + (size_t)ii * 32 + lane);
        const __half2 iv0 = __floats2half2_rn(iv.x, iv.y);
        const __half2 iv1 = __floats2half2_rn(iv.z, iv.w);

        const uint2* __restrict__ obase = reinterpret_cast<const uint2*>(g_oemb_h);

        // Per-lane dot partials for all 21 scores (padded to 32 for the reduce).
        float p[32];
        #pragma unroll
        for (int k = 0; k < SCORES; k++) {
            const int ridx = __shfl_sync(FULL_MASK, idx_all, k);
            const uint2 u = __ldg(obase + (size_t)ridx * 32 + lane);
            const __half2 hlo = *reinterpret_cast<const __half2*>(&u.x);
            const __half2 hhi = *reinterpret_cast<const __half2*>(&u.y);
            __half2 pr = __hmul2(hlo, iv0);
            pr = __hfma2(hhi, iv1, pr);
            p[k] = __low2float(pr) + __high2float(pr);
        }
        #pragma unroll
        for (int k = SCORES; k < 32; k++) p[k] = 0.0f;

        // Transpose-reduce: 5 halving-exchange rounds (31 SHFL total).
        // Final: lane L holds the fully reduced score L.
        #pragma unroll
        for (int w = 16; w >= 1; w >>= 1) {
            const bool hi = (lane & w) != 0;
            #pragma unroll
            for (int k = 0; k < w; k++) {
                const float send = hi ? p[k]     : p[k + w];
                const float keep = hi ? p[k + w] : p[k];
                const float t = __shfl_xor_sync(FULL_MASK, send, w);
                p[k] = keep + t;
            }
        }
        const float score = p[0];

        // log_sigmoid in one warp-wide pass:
        //   lanes 0..19: logsig(-neg_score); lane 20: logsig(+pos_score)
        // stable form: logsig(x) = min(x,0) - log(1 + exp(-|x|))
        const float x  = (lane < NEG_K) ? -score : score;
        const float ax = fabsf(x);
        float ls = fminf(x, 0.0f) - __logf(1.0f + __expf(-ax));
        if (lane > NEG_K) ls = 0.0f;

        #pragma unroll
        for (int w = 16; w >= 1; w >>= 1)
            ls += __shfl_xor_sync(FULL_MASK, ls, w);

        warp_loss = ls;
    }

    // Block reduction: 8 warps -> one double atomic per block.
    __shared__ float wl[8];
    const int wib = threadIdx.x >> 5;
    if (lane == 0) wl[wib] = warp_loss;
    __syncthreads();

    if (threadIdx.x == 0) {
        double s = 0.0;
        #pragma unroll
        for (int i = 0; i < 8; i++) s += (double)wl[i];
        atomicAdd(&g_accum, s);
        __threadfence();

        // Ticket: atomicInc wraps to 0 when old == gridDim.x-1, so the counter
        // self-resets for the next replay.
        const unsigned int t = atomicInc(&g_ticket, gridDim.x - 1);
        if (t == gridDim.x - 1) {
            __threadfence();
            const double total = g_accum;   // all adds visible (fence + ticket order)
            out[0] = (float)(-total / (double)B);
            g_accum = 0.0;                  // reset for next replay
        }
    }
}

extern "C" void kernel_launch(void* const* d_in, const int* in_sizes, int n_in,
                              void* d_out, int out_size) {
    const int*   in_b  = (const int*)  d_in[0];
    const int*   out_b = (const int*)  d_in[1];
    const int*   neg   = (const int*)  d_in[2];
    const float* iemb  = (const float*)d_in[3];
    const float* oemb  = (const float*)d_in[4];

    const int B = in_sizes[0];  // 65536

    // 1) fp32 -> fp16 output table
    const int n8 = (VOCAB * EMBED) / 8;
    convert_kernel<<<(n8 + 255) / 256, 256>>>(oemb);

    // 2) fused main + finalize
    const int threads = 256;
    const int warps_per_block = threads / 32;
    const int blocks = (B + warps_per_block - 1) / warps_per_block;
    skipgram_kernel<<<blocks, threads>>>(in_b, out_b, neg, iemb, (float*)d_out, B);
}

// round 3
// speedup vs baseline: 1.2090x; 1.0825x over previous
#include <cuda_runtime.h>
#include <cuda_fp16.h>

#define FULL_MASK 0xffffffffu
#define NEG_K 20
#define VOCAB 100000
#define EMBED 128

// Scratch (device globals — no allocations allowed).
__device__ __half       g_oemb_h[VOCAB * EMBED];   // fp16 copy of output_emb (25.6 MB)
__device__ double       g_accum  = 0.0;
__device__ unsigned int g_ticket = 0;

// ---------------------------------------------------------------------------
// Convert output_emb fp32 -> fp16 (every replay; pure function of input).
// ---------------------------------------------------------------------------
__global__ __launch_bounds__(256)
void convert_kernel(const float* __restrict__ oemb) {
    const int n8 = (VOCAB * EMBED) / 8;
    int i = blockIdx.x * blockDim.x + threadIdx.x;
    if (i >= n8) return;

    const float4* __restrict__ src = reinterpret_cast<const float4*>(oemb);
    float4 a = __ldg(src + 2 * i);
    float4 b = __ldg(src + 2 * i + 1);

    __half2 h0 = __floats2half2_rn(a.x, a.y);
    __half2 h1 = __floats2half2_rn(a.z, a.w);
    __half2 h2 = __floats2half2_rn(b.x, b.y);
    __half2 h3 = __floats2half2_rn(b.z, b.w);

    uint4 v;
    v.x = *reinterpret_cast<unsigned int*>(&h0);
    v.y = *reinterpret_cast<unsigned int*>(&h1);
    v.z = *reinterpret_cast<unsigned int*>(&h2);
    v.w = *reinterpret_cast<unsigned int*>(&h3);
    reinterpret_cast<uint4*>(g_oemb_h)[i] = v;
}

__device__ __forceinline__ __half2 shfl_xor_h2(__half2 v, int w) {
    int i = *reinterpret_cast<int*>(&v);
    i = __shfl_xor_sync(FULL_MASK, i, w);
    return *reinterpret_cast<__half2*>(&i);
}

// ---------------------------------------------------------------------------
// Main kernel: TWO examples per warp, one per 16-lane half.
// Each lane owns dims [8*hl, 8*hl+8) of its half's example:
//   output rows (fp16): one uint4 (8 halves) per lane  -> full row = 16 lanes
//   input row  (fp32):  two float4 per lane, converted to 4x half2
// Dot partials stay packed in half2 through the whole shuffle reduction.
// Last block finalizes: out[0] = -sum / B.
// ---------------------------------------------------------------------------
__global__ __launch_bounds__(256)
void skipgram_kernel(const int* __restrict__ in_b,
                     const int* __restrict__ out_b,
                     const int* __restrict__ neg,
                     const float* __restrict__ iemb,
                     float* __restrict__ out,
                     int B)
{
    const int warp = (blockIdx.x * blockDim.x + threadIdx.x) >> 5;
    const int lane = threadIdx.x & 31;
    const int hl   = lane & 15;          // lane within half
    const int half = (lane >> 4) & 1;    // which example of the pair
    const int hbase = lane & 16;         // shuffle-source base for this half

    const int braw = warp * 2 + half;
    const bool valid = (braw < B);
    const int b = valid ? braw : (B - 1);   // clamp: all lanes stay converged

    // Index fetch, lane-distributed per half:
    //   idx_a: lane hl holds negative index hl (scores 0..15)
    //   idx_b: hl 0..3 hold negatives 16..19, hl==4 holds the positive
    int idx_a = neg[(size_t)b * NEG_K + hl < (size_t)B * NEG_K && hl < 16
                        ? (size_t)b * NEG_K + hl : 0];
    // (hl is always < 16; the expression above is just a safe clamp)
    idx_a = neg[(size_t)b * NEG_K + (hl < NEG_K ? hl : 0)];
    int idx_b = 0;
    if (hl < 4)       idx_b = neg[(size_t)b * NEG_K + 16 + hl];
    else if (hl == 4) idx_b = out_b[b];

    const int ii = in_b[b];   // uniform per half

    // Input-embedding chunk: 8 floats -> 4 half2
    const float4* __restrict__ ibase = reinterpret_cast<const float4*>(iemb);
    const float4 a4 = __ldg(ibase + (size_t)ii * 32 + 2 * hl);
    const float4 b4 = __ldg(ibase + (size_t)ii * 32 + 2 * hl + 1);
    const __half2 iv0 = __floats2half2_rn(a4.x, a4.y);
    const __half2 iv1 = __floats2half2_rn(a4.z, a4.w);
    const __half2 iv2 = __floats2half2_rn(b4.x, b4.y);
    const __half2 iv3 = __floats2half2_rn(b4.z, b4.w);

    const uint4* __restrict__ obase = reinterpret_cast<const uint4*>(g_oemb_h);

    // --- scores 0..15 partials (packed half2) ---
    __half2 p[16];
    #pragma unroll
    for (int k = 0; k < 16; k++) {
        const int ridx = __shfl_sync(FULL_MASK, idx_a, hbase | k);
        const uint4 u = __ldg(obase + (size_t)ridx * 16 + hl);
        const __half2 r0 = *reinterpret_cast<const __half2*>(&u.x);
        const __half2 r1 = *reinterpret_cast<const __half2*>(&u.y);
        const __half2 r2 = *reinterpret_cast<const __half2*>(&u.z);
        const __half2 r3 = *reinterpret_cast<const __half2*>(&u.w);
        __half2 acc = __hmul2(r0, iv0);
        acc = __hfma2(r1, iv1, acc);
        acc = __hfma2(r2, iv2, acc);
        acc = __hfma2(r3, iv3, acc);
        p[k] = acc;
    }

    // --- scores 16..20 partials ---
    __half2 pB[5];
    #pragma unroll
    for (int k = 0; k < 5; k++) {
        const int ridx = __shfl_sync(FULL_MASK, idx_b, hbase | k);
        const uint4 u = __ldg(obase + (size_t)ridx * 16 + hl);
        const __half2 r0 = *reinterpret_cast<const __half2*>(&u.x);
        const __half2 r1 = *reinterpret_cast<const __half2*>(&u.y);
        const __half2 r2 = *reinterpret_cast<const __half2*>(&u.z);
        const __half2 r3 = *reinterpret_cast<const __half2*>(&u.w);
        __half2 acc = __hmul2(r0, iv0);
        acc = __hfma2(r1, iv1, acc);
        acc = __hfma2(r2, iv2, acc);
        acc = __hfma2(r3, iv3, acc);
        pB[k] = acc;
    }

    // --- 16-wide transpose-reduce for scores 0..15: lane hl ends with score hl ---
    #pragma unroll
    for (int w = 8; w >= 1; w >>= 1) {
        const bool hi = (hl & w) != 0;
        #pragma unroll
        for (int k = 0; k < w; k++) {
            const __half2 send = hi ? p[k]     : p[k + w];
            const __half2 keep = hi ? p[k + w] : p[k];
            p[k] = __hadd2(keep, shfl_xor_h2(send, w));
        }
    }

    // --- butterfly all-reduce for scores 16..20 (within 16-lane half) ---
    #pragma unroll
    for (int k = 0; k < 5; k++) {
        #pragma unroll
        for (int w = 8; w >= 1; w >>= 1)
            pB[k] = __hadd2(pB[k], shfl_xor_h2(pB[k], w));
    }

    // Select this lane's B score (lane hl -> score 16+hl, hl<5)
    __half2 bsel = pB[0];
    if (hl == 1) bsel = pB[1];
    if (hl == 2) bsel = pB[2];
    if (hl == 3) bsel = pB[3];
    if (hl == 4) bsel = pB[4];

    const float sA = __low2float(p[0]) + __high2float(p[0]);   // score hl (0..15)
    const float sB = __low2float(bsel) + __high2float(bsel);   // score 16+hl

    // logsig(x) = min(x,0) - log(1 + exp(-|x|))
    // scores 0..19 are negatives (x = -s), score 20 is the positive (x = +s)
    const float xA = -sA;
    float lsA = fminf(xA, 0.0f) - __logf(1.0f + __expf(-fabsf(xA)));

    const float xB = (hl == 4) ? sB : -sB;
    float lsB = fminf(xB, 0.0f) - __logf(1.0f + __expf(-fabsf(xB)));
    if (hl > 4) lsB = 0.0f;

    float ls = lsA + lsB;
    if (!valid) ls = 0.0f;

    // Sum over the 16 lanes of this half.
    #pragma unroll
    for (int w = 8; w >= 1; w >>= 1)
        ls += __shfl_xor_sync(FULL_MASK, ls, w);

    // Block reduction: 16 halves per block -> one double atomic.
    __shared__ float wl[16];
    if (hl == 0) wl[threadIdx.x >> 4] = ls;
    __syncthreads();

    if (threadIdx.x == 0) {
        double s = 0.0;
        #pragma unroll
        for (int i = 0; i < 16; i++) s += (double)wl[i];
        atomicAdd(&g_accum, s);
        __threadfence();

        const unsigned int t = atomicInc(&g_ticket, gridDim.x - 1);
        if (t == gridDim.x - 1) {
            __threadfence();
            const double total = g_accum;
            out[0] = (float)(-total / (double)B);
            g_accum = 0.0;   // reset for next replay
        }
    }
}

extern "C" void kernel_launch(void* const* d_in, const int* in_sizes, int n_in,
                              void* d_out, int out_size) {
    const int*   in_b  = (const int*)  d_in[0];
    const int*   out_b = (const int*)  d_in[1];
    const int*   neg   = (const int*)  d_in[2];
    const float* iemb  = (const float*)d_in[3];
    const float* oemb  = (const float*)d_in[4];

    const int B = in_sizes[0];  // 65536

    const int n8 = (VOCAB * EMBED) / 8;
    convert_kernel<<<(n8 + 255) / 256, 256>>>(oemb);

    const int threads = 256;
    const int ex_per_block = (threads / 32) * 2;              // 16
    const int blocks = (B + ex_per_block - 1) / ex_per_block; // 4096
    skipgram_kernel<<<blocks, threads>>>(in_b, out_b, neg, iemb, (float*)d_out, B);
}

// round 4
// speedup vs baseline: 1.3543x; 1.1201x over previous
#include <cuda_runtime.h>
#include <cuda_fp16.h>
#include <cuda_fp8.h>

#define FULL_MASK 0xffffffffu
#define NEG_K 20
#define VOCAB 100000
#define EMBED 128
#define SCALE 128.0f
#define INV_SCALE (1.0f / 128.0f)

// Scratch (device globals — no allocations allowed).
__device__ unsigned char g_oemb8[VOCAB * EMBED];   // e4m3 copy of output_emb * 128 (12.8 MB)
__device__ double        g_accum  = 0.0;
__device__ unsigned int  g_ticket = 0;

// ---------------------------------------------------------------------------
// Convert output_emb fp32 -> e4m3 (scaled x128). Every replay; pure function
// of the input. Each thread: 16 floats in (4x float4), 16 fp8 out (1x uint4).
// ---------------------------------------------------------------------------
__global__ __launch_bounds__(256)
void convert_kernel(const float* __restrict__ oemb) {
    const int n16 = (VOCAB * EMBED) / 16;
    int i = blockIdx.x * blockDim.x + threadIdx.x;
    if (i >= n16) return;

    const float4* __restrict__ src = reinterpret_cast<const float4*>(oemb);
    unsigned int w[4];
    #pragma unroll
    for (int j = 0; j < 4; j++) {
        float4 a = __ldg(src + 4 * i + j);
        __nv_fp8x2_storage_t lo = __nv_cvt_float2_to_fp8x2(
            make_float2(a.x * SCALE, a.y * SCALE), __NV_SATFINITE, __NV_E4M3);
        __nv_fp8x2_storage_t hi = __nv_cvt_float2_to_fp8x2(
            make_float2(a.z * SCALE, a.w * SCALE), __NV_SATFINITE, __NV_E4M3);
        w[j] = (unsigned int)lo | ((unsigned int)hi << 16);
    }
    uint4 v = make_uint4(w[0], w[1], w[2], w[3]);
    reinterpret_cast<uint4*>(g_oemb8)[i] = v;
}

__device__ __forceinline__ __half2 shfl_xor_h2(__half2 v, int w) {
    int i = *reinterpret_cast<int*>(&v);
    i = __shfl_xor_sync(FULL_MASK, i, w);
    return *reinterpret_cast<__half2*>(&i);
}

__device__ __forceinline__ __half2 fp8x2_to_h2(unsigned short v) {
    __half2_raw r = __nv_cvt_fp8x2_to_halfraw2((__nv_fp8x2_storage_t)v, __NV_E4M3);
    return *reinterpret_cast<__half2*>(&r);
}

// dot-partial of one fp8 row chunk (8 values in a uint2) against 4 half2 of input
__device__ __forceinline__ __half2 dot8(uint2 u, __half2 iv0, __half2 iv1,
                                        __half2 iv2, __half2 iv3) {
    __half2 c0 = fp8x2_to_h2((unsigned short)(u.x & 0xffffu));
    __half2 c1 = fp8x2_to_h2((unsigned short)(u.x >> 16));
    __half2 c2 = fp8x2_to_h2((unsigned short)(u.y & 0xffffu));
    __half2 c3 = fp8x2_to_h2((unsigned short)(u.y >> 16));
    __half2 acc = __hmul2(c0, iv0);
    acc = __hfma2(c1, iv1, acc);
    acc = __hfma2(c2, iv2, acc);
    acc = __hfma2(c3, iv3, acc);
    return acc;
}

// ---------------------------------------------------------------------------
// Main kernel: TWO examples per warp, one per 16-lane half.
// Each lane owns dims [8*hl, 8*hl+8) of its half's example:
//   output rows (e4m3 x128): one uint2 (8 fp8) per lane -> full row = 128 B = 1 line
//   input row   (fp32):      two float4 per lane, converted to 4x half2
// Dot partials stay packed in half2 through the shuffle reductions.
// Last block finalizes: out[0] = -sum / B.
// ---------------------------------------------------------------------------
__global__ __launch_bounds__(256)
void skipgram_kernel(const int* __restrict__ in_b,
                     const int* __restrict__ out_b,
                     const int* __restrict__ neg,
                     const float* __restrict__ iemb,
                     float* __restrict__ out,
                     int B)
{
    const int warp = (blockIdx.x * blockDim.x + threadIdx.x) >> 5;
    const int lane = threadIdx.x & 31;
    const int hl   = lane & 15;          // lane within half
    const int half = (lane >> 4) & 1;    // which example of the pair
    const int hbase = lane & 16;         // shuffle-source base for this half

    const int braw = warp * 2 + half;
    const bool valid = (braw < B);
    const int b = valid ? braw : (B - 1);   // clamp: all lanes stay converged

    // Index fetch, lane-distributed per half:
    //   idx_a: lane hl holds negative index hl (scores 0..15)
    //   idx_b: hl 0..3 hold negatives 16..19, hl==4 holds the positive
    const int idx_a = neg[(size_t)b * NEG_K + (hl < NEG_K ? hl : 0)];
    int idx_b = 0;
    if (hl < 4)       idx_b = neg[(size_t)b * NEG_K + 16 + hl];
    else if (hl == 4) idx_b = out_b[b];

    const int ii = in_b[b];   // uniform per half

    // Input-embedding chunk: 8 floats -> 4 half2
    const float4* __restrict__ ibase = reinterpret_cast<const float4*>(iemb);
    const float4 a4 = __ldg(ibase + (size_t)ii * 32 + 2 * hl);
    const float4 b4 = __ldg(ibase + (size_t)ii * 32 + 2 * hl + 1);
    const __half2 iv0 = __floats2half2_rn(a4.x, a4.y);
    const __half2 iv1 = __floats2half2_rn(a4.z, a4.w);
    const __half2 iv2 = __floats2half2_rn(b4.x, b4.y);
    const __half2 iv3 = __floats2half2_rn(b4.z, b4.w);

    const uint2* __restrict__ obase = reinterpret_cast<const uint2*>(g_oemb8);

    // --- scores 0..15 partials (packed half2) ---
    __half2 p[16];
    #pragma unroll
    for (int k = 0; k < 16; k++) {
        const int ridx = __shfl_sync(FULL_MASK, idx_a, hbase | k);
        const uint2 u = __ldg(obase + (size_t)ridx * 16 + hl);
        p[k] = dot8(u, iv0, iv1, iv2, iv3);
    }

    // --- scores 16..20 partials ---
    __half2 pB[5];
    #pragma unroll
    for (int k = 0; k < 5; k++) {
        const int ridx = __shfl_sync(FULL_MASK, idx_b, hbase | k);
        const uint2 u = __ldg(obase + (size_t)ridx * 16 + hl);
        pB[k] = dot8(u, iv0, iv1, iv2, iv3);
    }

    // --- 16-wide transpose-reduce for scores 0..15: lane hl ends with score hl ---
    #pragma unroll
    for (int w = 8; w >= 1; w >>= 1) {
        const bool hi = (hl & w) != 0;
        #pragma unroll
        for (int k = 0; k < w; k++) {
            const __half2 send = hi ? p[k]     : p[k + w];
            const __half2 keep = hi ? p[k + w] : p[k];
            p[k] = __hadd2(keep, shfl_xor_h2(send, w));
        }
    }

    // --- butterfly all-reduce for scores 16..20 (within 16-lane half) ---
    #pragma unroll
    for (int k = 0; k < 5; k++) {
        #pragma unroll
        for (int w = 8; w >= 1; w >>= 1)
            pB[k] = __hadd2(pB[k], shfl_xor_h2(pB[k], w));
    }

    // Select this lane's B score (lane hl -> score 16+hl, hl<5)
    __half2 bsel = pB[0];
    if (hl == 1) bsel = pB[1];
    if (hl == 2) bsel = pB[2];
    if (hl == 3) bsel = pB[3];
    if (hl == 4) bsel = pB[4];

    // Undo the x128 table scale.
    const float sA = (__low2float(p[0]) + __high2float(p[0])) * INV_SCALE;
    const float sB = (__low2float(bsel) + __high2float(bsel)) * INV_SCALE;

    // logsig(x) = min(x,0) - log(1 + exp(-|x|))
    // scores 0..19 are negatives (x = -s), score 20 is the positive (x = +s)
    const float xA = -sA;
    float lsA = fminf(xA, 0.0f) - __logf(1.0f + __expf(-fabsf(xA)));

    const float xB = (hl == 4) ? sB : -sB;
    float lsB = fminf(xB, 0.0f) - __logf(1.0f + __expf(-fabsf(xB)));
    if (hl > 4) lsB = 0.0f;

    float ls = lsA + lsB;
    if (!valid) ls = 0.0f;

    // Sum over the 16 lanes of this half.
    #pragma unroll
    for (int w = 8; w >= 1; w >>= 1)
        ls += __shfl_xor_sync(FULL_MASK, ls, w);

    // Block reduction: 16 halves per block -> one double atomic.
    __shared__ float wl[16];
    if (hl == 0) wl[threadIdx.x >> 4] = ls;
    __syncthreads();

    if (threadIdx.x == 0) {
        double s = 0.0;
        #pragma unroll
        for (int i = 0; i < 16; i++) s += (double)wl[i];
        atomicAdd(&g_accum, s);
        __threadfence();

        const unsigned int t = atomicInc(&g_ticket, gridDim.x - 1);
        if (t == gridDim.x - 1) {
            __threadfence();
            const double total = g_accum;
            out[0] = (float)(-total / (double)B);
            g_accum = 0.0;   // reset for next replay
        }
    }
}

extern "C" void kernel_launch(void* const* d_in, const int* in_sizes, int n_in,
                              void* d_out, int out_size) {
    const int*   in_b  = (const int*)  d_in[0];
    const int*   out_b = (const int*)  d_in[1];
    const int*   neg   = (const int*)  d_in[2];
    const float* iemb  = (const float*)d_in[3];
    const float* oemb  = (const float*)d_in[4];

    const int B = in_sizes[0];  // 65536

    const int n16 = (VOCAB * EMBED) / 16;
    convert_kernel<<<(n16 + 255) / 256, 256>>>(oemb);

    const int threads = 256;
    const int ex_per_block = (threads / 32) * 2;              // 16
    const int blocks = (B + ex_per_block - 1) / ex_per_block; // 4096
    skipgram_kernel<<<blocks, threads>>>(in_b, out_b, neg, iemb, (float*)d_out, B);
}